// round 3
// baseline (speedup 1.0000x reference)
#include <cuda_runtime.h>
#include <cstdint>

#define N_E   200000
#define N_T   1000000
#define N_R   200
#define N_W2V 300
#define BB    64        // batch

// Ping-pong entity-major state buffers: (N_E, B) each. 2 x 51.2 MB static scratch.
__device__ __align__(256) float g_buf[2][(size_t)N_E * BB];
// Precomputed r for all 3 hops, relation-major: rt[h][j][b]
__device__ __align__(256) float g_rt[3][N_R * BB];

// ---------------------------------------------------------------------------
// Transpose x (B, N_E) -> g_buf[0] (N_E, B). 32-entity x 64-batch tiles in smem.
// ---------------------------------------------------------------------------
__global__ void transpose_in(const float* __restrict__ x) {
    __shared__ float tile[32][BB + 1];     // [e][b], pad -> conflict-free
    const int e0   = blockIdx.x * 32;
    const int tid  = threadIdx.x;          // 256 threads
    const int lane = tid & 31;
    const int warp = tid >> 5;

    // Load: warp w reads batch rows b = w, w+8, ... ; 32 consecutive e per row.
    for (int b = warp; b < BB; b += 8) {
        const int e = e0 + lane;
        tile[lane][b] = (e < N_E) ? x[(size_t)b * N_E + e] : 0.f;
    }
    __syncthreads();

    // Store: 64 b-lanes x 4 e-rows, coalesced 256B rows of g_buf[0].
    const int bl = tid & 63;
    for (int er = tid >> 6; er < 32; er += 4) {
        const int e = e0 + er;
        if (e < N_E) g_buf[0][(size_t)e * BB + bl] = tile[er][bl];
    }
}

// ---------------------------------------------------------------------------
// Final transpose g_buf[n_hop & 1] (N_E, B) -> out (B, N_E).
// ---------------------------------------------------------------------------
__global__ void transpose_out(float* __restrict__ out, const int* __restrict__ n_hop) {
    const float* __restrict__ src = g_buf[(*n_hop) & 1];
    __shared__ float tile[32][BB + 1];
    const int e0  = blockIdx.x * 32;
    const int tid = threadIdx.x;

    const int bl = tid & 63;
    for (int er = tid >> 6; er < 32; er += 4) {
        const int e = e0 + er;
        tile[er][bl] = (e < N_E) ? src[(size_t)e * BB + bl] : 0.f;
    }
    __syncthreads();

    const int lane = tid & 31;
    const int warp = tid >> 5;
    for (int b = warp; b < BB; b += 8) {
        const int e = e0 + lane;
        if (e < N_E) out[(size_t)b * N_E + e] = tile[lane][b];
    }
}

// ---------------------------------------------------------------------------
// r_h = q @ W_h + b_h for all 3 hops at once (r depends only on q).
// grid = 3 * N_R blocks, 64 threads. Thread i computes rt[h][j][i].
// ---------------------------------------------------------------------------
__global__ void compute_r(const float* __restrict__ q,
                          const float* __restrict__ W1, const float* __restrict__ b1,
                          const float* __restrict__ W2, const float* __restrict__ b2,
                          const float* __restrict__ W3, const float* __restrict__ b3) {
    const int h = blockIdx.x / N_R;
    const int j = blockIdx.x - h * N_R;
    const float* __restrict__ W  = (h == 0) ? W1 : (h == 1) ? W2 : W3;
    const float* __restrict__ bv = (h == 0) ? b1 : (h == 1) ? b2 : b3;

    __shared__ float Wc[N_W2V];
    const int i = threadIdx.x;                     // 0..63 (batch row)
    for (int k = i; k < N_W2V; k += 64)
        Wc[k] = W[(size_t)k * N_R + j];            // W[k][j], row-major (N_W2V, N_R)
    __syncthreads();

    float acc = bv[j];
    const float* __restrict__ qi = q + (size_t)i * N_W2V;
#pragma unroll 4
    for (int k = 0; k < N_W2V; ++k)
        acc = fmaf(qi[k], Wc[k], acc);
    g_rt[h][j * BB + i] = acc;
}

// ---------------------------------------------------------------------------
// Zero the target buffer for hop `hop` (only if hop is active).
// ---------------------------------------------------------------------------
__global__ void zero_buf(int hop, const int* __restrict__ n_hop) {
    if (hop >= *n_hop) return;
    float4* __restrict__ p = reinterpret_cast<float4*>(g_buf[(hop + 1) & 1]);
    const size_t n = (size_t)N_E * BB / 4;
    const size_t stride = (size_t)gridDim.x * blockDim.x;
    for (size_t i = (size_t)blockIdx.x * blockDim.x + threadIdx.x; i < n; i += stride)
        p[i] = make_float4(0.f, 0.f, 0.f, 0.f);
}

// ---------------------------------------------------------------------------
// One hop: for each triple t, yt[obj[t]] += xt[subj[t]] * rt[rel[t]]
// 16 threads per triple, float4 per lane, vector red.global.add.
// ---------------------------------------------------------------------------
__global__ void hop_scatter(const int* __restrict__ subj,
                            const int* __restrict__ rel,
                            const int* __restrict__ obj,
                            int hop, const int* __restrict__ n_hop) {
    if (hop >= *n_hop) return;
    const float* __restrict__ xt = g_buf[hop & 1];
    float*       __restrict__ yt = g_buf[(hop + 1) & 1];
    const float* __restrict__ rt = g_rt[hop];

    const int tid = blockIdx.x * blockDim.x + threadIdx.x;
    const int t   = tid >> 4;                 // triple index
    if (t >= N_T) return;
    const int j   = (tid & 15) << 2;          // float offset within the 64-wide row

    const int s  = __ldg(subj + t);
    const int rl = __ldg(rel  + t);
    const int o  = __ldg(obj  + t);

    const float4 xv = *reinterpret_cast<const float4*>(xt + (size_t)s * BB + j);
    const float4 rv = __ldg(reinterpret_cast<const float4*>(rt + rl * BB + j));

    const float4 m = make_float4(xv.x * rv.x, xv.y * rv.y, xv.z * rv.z, xv.w * rv.w);
    float* dst = yt + (size_t)o * BB + j;
    asm volatile("red.global.add.v4.f32 [%0], {%1,%2,%3,%4};"
                 :: "l"(dst), "f"(m.x), "f"(m.y), "f"(m.z), "f"(m.w)
                 : "memory");
}

// ---------------------------------------------------------------------------
// Launch
// ---------------------------------------------------------------------------
extern "C" void kernel_launch(void* const* d_in, const int* in_sizes, int n_in,
                              void* d_out, int out_size) {
    const float* x    = (const float*)d_in[0];
    const float* q    = (const float*)d_in[1];
    const float* W1   = (const float*)d_in[2];
    const float* b1   = (const float*)d_in[3];
    const float* W2   = (const float*)d_in[4];
    const float* b2   = (const float*)d_in[5];
    const float* W3   = (const float*)d_in[6];
    const float* b3   = (const float*)d_in[7];
    const int*   subj = (const int*)d_in[8];
    const int*   rel  = (const int*)d_in[9];
    const int*   obj  = (const int*)d_in[10];
    const int*   nhop = (const int*)d_in[11];
    float*       out  = (float*)d_out;

    const int tb = (N_E + 31) / 32;           // 6250 tile blocks

    transpose_in<<<tb, 256>>>(x);
    compute_r<<<3 * N_R, 64>>>(q, W1, b1, W2, b2, W3, b3);

    const int scatter_blocks = (N_T * 16 + 255) / 256;   // 62500
    for (int h = 0; h < 3; ++h) {
        zero_buf<<<148 * 16, 256>>>(h, nhop);
        hop_scatter<<<scatter_blocks, 256>>>(subj, rel, obj, h, nhop);
    }

    transpose_out<<<tb, 256>>>(out, nhop);
}

// round 4
// speedup vs baseline: 1.5937x; 1.5937x over previous
#include <cuda_runtime.h>
#include <cstdint>

#define N_E   200000
#define N_T   1000000
#define N_R   200
#define N_W2V 300
#define BB    64        // batch

// Ping-pong entity-major state buffers: (N_E, B) each. 2 x 51.2 MB static scratch.
__device__ __align__(256) float g_buf[2][(size_t)N_E * BB];
// Precomputed r for all 3 hops, relation-major: rt[h][j][b]
__device__ __align__(256) float g_rt[3][N_R * BB];

// ---------------------------------------------------------------------------
// Transpose x (B, N_E) -> g_buf[0] (N_E, B). 32-entity x 64-batch tiles in smem.
// ---------------------------------------------------------------------------
__global__ void transpose_in(const float* __restrict__ x) {
    __shared__ float tile[32][BB + 1];     // [e][b], pad -> conflict-free
    const int e0   = blockIdx.x * 32;
    const int tid  = threadIdx.x;          // 256 threads
    const int lane = tid & 31;
    const int warp = tid >> 5;

    // Load: warp w reads batch rows b = w, w+8, ... ; 32 consecutive e per row.
    for (int b = warp; b < BB; b += 8) {
        const int e = e0 + lane;
        tile[lane][b] = (e < N_E) ? x[(size_t)b * N_E + e] : 0.f;
    }
    __syncthreads();

    // Store: 16 float4-lanes x 16 e-rows per pass, coalesced 256B rows.
    const int f4 = tid & 15;               // float4 index within row
    for (int er = tid >> 4; er < 32; er += 16) {
        const int e = e0 + er;
        if (e < N_E) {
            float4 v = make_float4(tile[er][f4 * 4 + 0], tile[er][f4 * 4 + 1],
                                   tile[er][f4 * 4 + 2], tile[er][f4 * 4 + 3]);
            reinterpret_cast<float4*>(&g_buf[0][(size_t)e * BB])[f4] = v;
        }
    }
}

// ---------------------------------------------------------------------------
// Final transpose g_buf[n_hop & 1] (N_E, B) -> out (B, N_E).
// ---------------------------------------------------------------------------
__global__ void transpose_out(float* __restrict__ out, const int* __restrict__ n_hop) {
    const float* __restrict__ src = g_buf[(*n_hop) & 1];
    __shared__ float tile[32][BB + 1];
    const int e0  = blockIdx.x * 32;
    const int tid = threadIdx.x;

    const int f4 = tid & 15;
    for (int er = tid >> 4; er < 32; er += 16) {
        const int e = e0 + er;
        float4 v = make_float4(0.f, 0.f, 0.f, 0.f);
        if (e < N_E)
            v = reinterpret_cast<const float4*>(&src[(size_t)e * BB])[f4];
        tile[er][f4 * 4 + 0] = v.x;
        tile[er][f4 * 4 + 1] = v.y;
        tile[er][f4 * 4 + 2] = v.z;
        tile[er][f4 * 4 + 3] = v.w;
    }
    __syncthreads();

    const int lane = tid & 31;
    const int warp = tid >> 5;
    for (int b = warp; b < BB; b += 8) {
        const int e = e0 + lane;
        if (e < N_E) out[(size_t)b * N_E + e] = tile[lane][b];
    }
}

// ---------------------------------------------------------------------------
// r_h = q @ W_h + b_h for all 3 hops at once (r depends only on q).
// grid = 3 * N_R blocks, 64 threads. Thread i computes rt[h][j][i].
// ---------------------------------------------------------------------------
__global__ void compute_r(const float* __restrict__ q,
                          const float* __restrict__ W1, const float* __restrict__ b1,
                          const float* __restrict__ W2, const float* __restrict__ b2,
                          const float* __restrict__ W3, const float* __restrict__ b3) {
    const int h = blockIdx.x / N_R;
    const int j = blockIdx.x - h * N_R;
    const float* __restrict__ W  = (h == 0) ? W1 : (h == 1) ? W2 : W3;
    const float* __restrict__ bv = (h == 0) ? b1 : (h == 1) ? b2 : b3;

    __shared__ float Wc[N_W2V];
    const int i = threadIdx.x;                     // 0..63 (batch row)
    for (int k = i; k < N_W2V; k += 64)
        Wc[k] = W[(size_t)k * N_R + j];            // W[k][j], row-major (N_W2V, N_R)
    __syncthreads();

    float acc = bv[j];
    const float* __restrict__ qi = q + (size_t)i * N_W2V;
#pragma unroll 4
    for (int k = 0; k < N_W2V; ++k)
        acc = fmaf(qi[k], Wc[k], acc);
    g_rt[h][j * BB + i] = acc;
}

// ---------------------------------------------------------------------------
// Zero the target buffer for hop `hop` (only if hop is active).
// ---------------------------------------------------------------------------
__global__ void zero_buf(int hop, const int* __restrict__ n_hop) {
    if (hop >= *n_hop) return;
    float4* __restrict__ p = reinterpret_cast<float4*>(g_buf[(hop + 1) & 1]);
    const size_t n = (size_t)N_E * BB / 4;
    const size_t stride = (size_t)gridDim.x * blockDim.x;
    for (size_t i = (size_t)blockIdx.x * blockDim.x + threadIdx.x; i < n; i += stride)
        p[i] = make_float4(0.f, 0.f, 0.f, 0.f);
}

// ---------------------------------------------------------------------------
// One hop: yt[obj[t]] += xt[subj[t]] * rt[rel[t]]  (per 64-wide batch row)
// 16 threads per triple-group; each group handles 4 consecutive triples to
// get 4 independent gathers in flight per thread (MLP=4).
// ---------------------------------------------------------------------------
__device__ __forceinline__ void red_v4(float* dst, float4 m) {
    asm volatile("red.global.add.v4.f32 [%0], {%1,%2,%3,%4};"
                 :: "l"(dst), "f"(m.x), "f"(m.y), "f"(m.z), "f"(m.w)
                 : "memory");
}

__global__ void __launch_bounds__(128)
hop_scatter(const int* __restrict__ subj,
            const int* __restrict__ rel,
            const int* __restrict__ obj,
            int hop, const int* __restrict__ n_hop) {
    if (hop >= *n_hop) return;
    const float* __restrict__ xt = g_buf[hop & 1];
    float*       __restrict__ yt = g_buf[(hop + 1) & 1];
    const float* __restrict__ rt = g_rt[hop];

    const int tid = blockIdx.x * blockDim.x + threadIdx.x;
    const int g   = tid >> 4;                  // triple group of 4
    if (g >= N_T / 4) return;
    const int j   = (tid & 15) << 2;           // float offset within 64-wide row
    const int t0  = g << 2;

    // One int4 per index array covers all 4 triples (broadcast within group).
    const int4 s4 = *reinterpret_cast<const int4*>(subj + t0);
    const int4 r4 = *reinterpret_cast<const int4*>(rel  + t0);
    const int4 o4 = *reinterpret_cast<const int4*>(obj  + t0);

    // 4 independent gathers issued back-to-back.
    const float4 x0 = *reinterpret_cast<const float4*>(xt + (size_t)s4.x * BB + j);
    const float4 x1 = *reinterpret_cast<const float4*>(xt + (size_t)s4.y * BB + j);
    const float4 x2 = *reinterpret_cast<const float4*>(xt + (size_t)s4.z * BB + j);
    const float4 x3 = *reinterpret_cast<const float4*>(xt + (size_t)s4.w * BB + j);

    const float4 v0 = __ldg(reinterpret_cast<const float4*>(rt + r4.x * BB + j));
    const float4 v1 = __ldg(reinterpret_cast<const float4*>(rt + r4.y * BB + j));
    const float4 v2 = __ldg(reinterpret_cast<const float4*>(rt + r4.z * BB + j));
    const float4 v3 = __ldg(reinterpret_cast<const float4*>(rt + r4.w * BB + j));

    red_v4(yt + (size_t)o4.x * BB + j,
           make_float4(x0.x * v0.x, x0.y * v0.y, x0.z * v0.z, x0.w * v0.w));
    red_v4(yt + (size_t)o4.y * BB + j,
           make_float4(x1.x * v1.x, x1.y * v1.y, x1.z * v1.z, x1.w * v1.w));
    red_v4(yt + (size_t)o4.z * BB + j,
           make_float4(x2.x * v2.x, x2.y * v2.y, x2.z * v2.z, x2.w * v2.w));
    red_v4(yt + (size_t)o4.w * BB + j,
           make_float4(x3.x * v3.x, x3.y * v3.y, x3.z * v3.z, x3.w * v3.w));
}

// ---------------------------------------------------------------------------
// Launch
// ---------------------------------------------------------------------------
extern "C" void kernel_launch(void* const* d_in, const int* in_sizes, int n_in,
                              void* d_out, int out_size) {
    const float* x    = (const float*)d_in[0];
    const float* q    = (const float*)d_in[1];
    const float* W1   = (const float*)d_in[2];
    const float* b1   = (const float*)d_in[3];
    const float* W2   = (const float*)d_in[4];
    const float* b2   = (const float*)d_in[5];
    const float* W3   = (const float*)d_in[6];
    const float* b3   = (const float*)d_in[7];
    const int*   subj = (const int*)d_in[8];
    const int*   rel  = (const int*)d_in[9];
    const int*   obj  = (const int*)d_in[10];
    const int*   nhop = (const int*)d_in[11];
    float*       out  = (float*)d_out;

    const int tb = (N_E + 31) / 32;           // 6250 tile blocks

    transpose_in<<<tb, 256>>>(x);
    compute_r<<<3 * N_R, 64>>>(q, W1, b1, W2, b2, W3, b3);

    // (N_T/4 groups) * 16 threads = 4M threads, 128-thread blocks.
    const int scatter_blocks = (N_T / 4 * 16 + 127) / 128;   // 31250
    for (int h = 0; h < 3; ++h) {
        zero_buf<<<148 * 16, 256>>>(h, nhop);
        hop_scatter<<<scatter_blocks, 128>>>(subj, rel, obj, h, nhop);
    }

    transpose_out<<<tb, 256>>>(out, nhop);
}

// round 7
// speedup vs baseline: 1.6129x; 1.0121x over previous
#include <cuda_runtime.h>
#include <cstdint>

#define N_E   200000
#define N_T   1000000
#define N_R   200
#define N_W2V 300
#define BB    64        // batch

// Ping-pong entity-major state buffers: (N_E, B) each. 2 x 51.2 MB static scratch.
__device__ __align__(256) float g_buf[2][(size_t)N_E * BB];
// Precomputed r for all 3 hops, relation-major: rt[h][j][b]
__device__ __align__(256) float g_rt[3][N_R * BB];

// ---------------------------------------------------------------------------
// Transpose x (B, N_E) -> g_buf[0] (N_E, B). 32-entity x 64-batch tiles in smem.
// ---------------------------------------------------------------------------
__global__ void transpose_in(const float* __restrict__ x) {
    __shared__ float tile[32][BB + 1];     // [e][b], pad -> conflict-free
    const int e0   = blockIdx.x * 32;
    const int tid  = threadIdx.x;          // 256 threads
    const int lane = tid & 31;
    const int warp = tid >> 5;

    for (int b = warp; b < BB; b += 8) {
        const int e = e0 + lane;
        tile[lane][b] = (e < N_E) ? x[(size_t)b * N_E + e] : 0.f;
    }
    __syncthreads();

    const int f4 = tid & 15;               // float4 index within row
    for (int er = tid >> 4; er < 32; er += 16) {
        const int e = e0 + er;
        if (e < N_E) {
            float4 v = make_float4(tile[er][f4 * 4 + 0], tile[er][f4 * 4 + 1],
                                   tile[er][f4 * 4 + 2], tile[er][f4 * 4 + 3]);
            reinterpret_cast<float4*>(&g_buf[0][(size_t)e * BB])[f4] = v;
        }
    }
}

// ---------------------------------------------------------------------------
// Final transpose g_buf[n_hop & 1] (N_E, B) -> out (B, N_E).
// ---------------------------------------------------------------------------
__global__ void transpose_out(float* __restrict__ out, const int* __restrict__ n_hop) {
    const float* __restrict__ src = g_buf[(*n_hop) & 1];
    __shared__ float tile[32][BB + 1];
    const int e0  = blockIdx.x * 32;
    const int tid = threadIdx.x;

    const int f4 = tid & 15;
    for (int er = tid >> 4; er < 32; er += 16) {
        const int e = e0 + er;
        float4 v = make_float4(0.f, 0.f, 0.f, 0.f);
        if (e < N_E)
            v = reinterpret_cast<const float4*>(&src[(size_t)e * BB])[f4];
        tile[er][f4 * 4 + 0] = v.x;
        tile[er][f4 * 4 + 1] = v.y;
        tile[er][f4 * 4 + 2] = v.z;
        tile[er][f4 * 4 + 3] = v.w;
    }
    __syncthreads();

    const int lane = tid & 31;
    const int warp = tid >> 5;
    for (int b = warp; b < BB; b += 8) {
        const int e = e0 + lane;
        if (e < N_E) out[(size_t)b * N_E + e] = tile[lane][b];
    }
}

// ---------------------------------------------------------------------------
// r_h = q @ W_h + b_h for all 3 hops at once (r depends only on q).
// ---------------------------------------------------------------------------
__global__ void compute_r(const float* __restrict__ q,
                          const float* __restrict__ W1, const float* __restrict__ b1,
                          const float* __restrict__ W2, const float* __restrict__ b2,
                          const float* __restrict__ W3, const float* __restrict__ b3) {
    const int h = blockIdx.x / N_R;
    const int j = blockIdx.x - h * N_R;
    const float* __restrict__ W  = (h == 0) ? W1 : (h == 1) ? W2 : W3;
    const float* __restrict__ bv = (h == 0) ? b1 : (h == 1) ? b2 : b3;

    __shared__ float Wc[N_W2V];
    const int i = threadIdx.x;                     // 0..63 (batch row)
    for (int k = i; k < N_W2V; k += 64)
        Wc[k] = W[(size_t)k * N_R + j];            // W[k][j], row-major (N_W2V, N_R)
    __syncthreads();

    float acc = bv[j];
    const float* __restrict__ qi = q + (size_t)i * N_W2V;
#pragma unroll 4
    for (int k = 0; k < N_W2V; ++k)
        acc = fmaf(qi[k], Wc[k], acc);
    g_rt[h][j * BB + i] = acc;
}

// ---------------------------------------------------------------------------
// Zero the target buffer for hop `hop` (only if hop is active).
// ---------------------------------------------------------------------------
__global__ void zero_buf(int hop, const int* __restrict__ n_hop) {
    if (hop >= *n_hop) return;
    float4* __restrict__ p = reinterpret_cast<float4*>(g_buf[(hop + 1) & 1]);
    const size_t n = (size_t)N_E * BB / 4;
    const size_t stride = (size_t)gridDim.x * blockDim.x;
    for (size_t i = (size_t)blockIdx.x * blockDim.x + threadIdx.x; i < n; i += stride)
        p[i] = make_float4(0.f, 0.f, 0.f, 0.f);
}

// ---------------------------------------------------------------------------
// One hop: yt[obj[t]] += xt[subj[t]] * rt[rel[t]]  (per 64-wide batch row)
// 16 threads per group of 4 consecutive triples. ALL 8 loads (4 gathers +
// 4 rt rows) are issued and their products computed into live registers
// BEFORE the first red — the reds' "memory" clobbers are full compiler
// barriers, so any load after a red cannot be hoisted. launch_bounds(128,8)
// gives ptxas the ~64-reg budget needed to keep everything live.
// ---------------------------------------------------------------------------
__device__ __forceinline__ void red_v4(float* dst, float4 m) {
    asm volatile("red.global.add.v4.f32 [%0], {%1,%2,%3,%4};"
                 :: "l"(dst), "f"(m.x), "f"(m.y), "f"(m.z), "f"(m.w)
                 : "memory");
}

__device__ __forceinline__ int4 ldcs_int4(const int* p) {
    int4 v;
    asm volatile("ld.global.cs.v4.s32 {%0,%1,%2,%3}, [%4];"
                 : "=r"(v.x), "=r"(v.y), "=r"(v.z), "=r"(v.w) : "l"(p));
    return v;
}

__global__ void __launch_bounds__(128, 8)
hop_scatter(const int* __restrict__ subj,
            const int* __restrict__ rel,
            const int* __restrict__ obj,
            int hop, const int* __restrict__ n_hop) {
    if (hop >= *n_hop) return;
    const float* __restrict__ xt = g_buf[hop & 1];
    float*       __restrict__ yt = g_buf[(hop + 1) & 1];
    const float* __restrict__ rt = g_rt[hop];

    const int tid = blockIdx.x * blockDim.x + threadIdx.x;
    const int g   = tid >> 4;                  // triple group of 4
    if (g >= N_T / 4) return;
    const int j   = (tid & 15) << 2;           // float offset within 64-wide row
    const int t0  = g << 2;

    // Index loads: streaming (evict-first) so the 12MB of indices don't
    // thrash the L2-resident 102MB state.
    const int4 s4 = ldcs_int4(subj + t0);
    const int4 r4 = ldcs_int4(rel  + t0);
    const int4 o4 = ldcs_int4(obj  + t0);

    // 4 independent gathers (long-latency) issued back-to-back.
    const float4 x0 = *reinterpret_cast<const float4*>(xt + (size_t)s4.x * BB + j);
    const float4 x1 = *reinterpret_cast<const float4*>(xt + (size_t)s4.y * BB + j);
    const float4 x2 = *reinterpret_cast<const float4*>(xt + (size_t)s4.z * BB + j);
    const float4 x3 = *reinterpret_cast<const float4*>(xt + (size_t)s4.w * BB + j);

    // 4 rt rows (L1-resident, 51KB table).
    const float4 v0 = __ldg(reinterpret_cast<const float4*>(rt + r4.x * BB + j));
    const float4 v1 = __ldg(reinterpret_cast<const float4*>(rt + r4.y * BB + j));
    const float4 v2 = __ldg(reinterpret_cast<const float4*>(rt + r4.z * BB + j));
    const float4 v3 = __ldg(reinterpret_cast<const float4*>(rt + r4.w * BB + j));

    // All products computed before any red (keeps all loads batched).
    const float4 m0 = make_float4(x0.x * v0.x, x0.y * v0.y, x0.z * v0.z, x0.w * v0.w);
    const float4 m1 = make_float4(x1.x * v1.x, x1.y * v1.y, x1.z * v1.z, x1.w * v1.w);
    const float4 m2 = make_float4(x2.x * v2.x, x2.y * v2.y, x2.z * v2.z, x2.w * v2.w);
    const float4 m3 = make_float4(x3.x * v3.x, x3.y * v3.y, x3.z * v3.z, x3.w * v3.w);

    float* d0 = yt + (size_t)o4.x * BB + j;
    float* d1 = yt + (size_t)o4.y * BB + j;
    float* d2 = yt + (size_t)o4.z * BB + j;
    float* d3 = yt + (size_t)o4.w * BB + j;

    red_v4(d0, m0);
    red_v4(d1, m1);
    red_v4(d2, m2);
    red_v4(d3, m3);
}

// ---------------------------------------------------------------------------
// Launch
// ---------------------------------------------------------------------------
extern "C" void kernel_launch(void* const* d_in, const int* in_sizes, int n_in,
                              void* d_out, int out_size) {
    const float* x    = (const float*)d_in[0];
    const float* q    = (const float*)d_in[1];
    const float* W1   = (const float*)d_in[2];
    const float* b1   = (const float*)d_in[3];
    const float* W2   = (const float*)d_in[4];
    const float* b2   = (const float*)d_in[5];
    const float* W3   = (const float*)d_in[6];
    const float* b3   = (const float*)d_in[7];
    const int*   subj = (const int*)d_in[8];
    const int*   rel  = (const int*)d_in[9];
    const int*   obj  = (const int*)d_in[10];
    const int*   nhop = (const int*)d_in[11];
    float*       out  = (float*)d_out;

    const int tb = (N_E + 31) / 32;           // 6250 tile blocks

    transpose_in<<<tb, 256>>>(x);
    compute_r<<<3 * N_R, 64>>>(q, W1, b1, W2, b2, W3, b3);

    const int scatter_blocks = (N_T / 4 * 16 + 127) / 128;   // 31250
    for (int h = 0; h < 3; ++h) {
        zero_buf<<<148 * 16, 256>>>(h, nhop);
        hop_scatter<<<scatter_blocks, 128>>>(subj, rel, obj, h, nhop);
    }

    transpose_out<<<tb, 256>>>(out, nhop);
}

// round 9
// speedup vs baseline: 1.6692x; 1.0349x over previous
#include <cuda_runtime.h>
#include <cuda_fp16.h>
#include <cstdint>

#define N_E   200000
#define N_T   1000000
#define N_R   200
#define N_W2V 300
#define BB    64        // batch

// fp16 gather-side state: (N_E, 64) halves, 128B rows. 25.6 MB.
__device__ __align__(256) __half g_x16[(size_t)N_E * BB];
// fp32 scatter-side accumulator: (N_E, 64) floats, 256B rows. 51.2 MB.
__device__ __align__(256) float  g_y32[(size_t)N_E * BB];
// Precomputed r for all 3 hops, relation-major fp16: rt[h][j][b]
__device__ __align__(256) __half g_rt16[3][N_R * BB];

struct __align__(8) h4 { __half2 a, b; };   // 4 halves = 8 bytes

// ---------------------------------------------------------------------------
// Transpose x (B, N_E) f32 -> g_x16 (N_E, 64) fp16, AND zero g_y32.
// ---------------------------------------------------------------------------
__global__ void transpose_in(const float* __restrict__ x) {
    __shared__ float tile[32][BB + 1];     // [e][b], pad -> conflict-free
    const int e0   = blockIdx.x * 32;
    const int tid  = threadIdx.x;          // 256 threads
    const int lane = tid & 31;
    const int warp = tid >> 5;

    for (int b = warp; b < BB; b += 8) {
        const int e = e0 + lane;
        tile[lane][b] = (e < N_E) ? x[(size_t)b * N_E + e] : 0.f;
    }

    // Zero my slice of g_y32 while the tile loads are in flight.
    // 6250 blocks * 512 float4 = 3.2M float4 = exactly N_E*BB floats.
    {
        float4* __restrict__ y4 = reinterpret_cast<float4*>(g_y32);
        const size_t base = (size_t)blockIdx.x * 512 + tid;
        const float4 z = make_float4(0.f, 0.f, 0.f, 0.f);
        y4[base]       = z;
        y4[base + 256] = z;
    }
    __syncthreads();

    // Store: 16 lanes x 8B per 128B fp16 row.
    const int l16 = tid & 15;
    for (int er = tid >> 4; er < 32; er += 16) {
        const int e = e0 + er;
        if (e < N_E) {
            h4 v;
            v.a = __floats2half2_rn(tile[er][l16 * 4 + 0], tile[er][l16 * 4 + 1]);
            v.b = __floats2half2_rn(tile[er][l16 * 4 + 2], tile[er][l16 * 4 + 3]);
            reinterpret_cast<h4*>(g_x16 + (size_t)e * BB)[l16] = v;
        }
    }
}

// ---------------------------------------------------------------------------
// Final transpose g_y32 (N_E, 64) f32 -> out (B, N_E).
// ---------------------------------------------------------------------------
__global__ void transpose_out(float* __restrict__ out) {
    __shared__ float tile[32][BB + 1];
    const int e0  = blockIdx.x * 32;
    const int tid = threadIdx.x;

    const int f4 = tid & 15;
    for (int er = tid >> 4; er < 32; er += 16) {
        const int e = e0 + er;
        float4 v = make_float4(0.f, 0.f, 0.f, 0.f);
        if (e < N_E)
            v = reinterpret_cast<const float4*>(&g_y32[(size_t)e * BB])[f4];
        tile[er][f4 * 4 + 0] = v.x;
        tile[er][f4 * 4 + 1] = v.y;
        tile[er][f4 * 4 + 2] = v.z;
        tile[er][f4 * 4 + 3] = v.w;
    }
    __syncthreads();

    const int lane = tid & 31;
    const int warp = tid >> 5;
    for (int b = warp; b < BB; b += 8) {
        const int e = e0 + lane;
        if (e < N_E) out[(size_t)b * N_E + e] = tile[lane][b];
    }
}

// ---------------------------------------------------------------------------
// r_h = q @ W_h + b_h for all 3 hops at once, stored fp16.
// ---------------------------------------------------------------------------
__global__ void compute_r(const float* __restrict__ q,
                          const float* __restrict__ W1, const float* __restrict__ b1,
                          const float* __restrict__ W2, const float* __restrict__ b2,
                          const float* __restrict__ W3, const float* __restrict__ b3) {
    const int h = blockIdx.x / N_R;
    const int j = blockIdx.x - h * N_R;
    const float* __restrict__ W  = (h == 0) ? W1 : (h == 1) ? W2 : W3;
    const float* __restrict__ bv = (h == 0) ? b1 : (h == 1) ? b2 : b3;

    __shared__ float Wc[N_W2V];
    const int i = threadIdx.x;                     // 0..63 (batch row)
    for (int k = i; k < N_W2V; k += 64)
        Wc[k] = W[(size_t)k * N_R + j];            // W[k][j], row-major (N_W2V, N_R)
    __syncthreads();

    float acc = bv[j];
    const float* __restrict__ qi = q + (size_t)i * N_W2V;
#pragma unroll 4
    for (int k = 0; k < N_W2V; ++k)
        acc = fmaf(qi[k], Wc[k], acc);
    g_rt16[h][j * BB + i] = __float2half_rn(acc);
}

// ---------------------------------------------------------------------------
// Between hops: x16 = fp16(y32); y32 = 0. Runs only if hop+1 < n_hop.
// One float4 (4 floats) per thread: 3.2M threads.
// ---------------------------------------------------------------------------
__global__ void __launch_bounds__(256)
convert_zero(int hop, const int* __restrict__ n_hop) {
    if (hop + 1 >= *n_hop) return;
    const size_t i = (size_t)blockIdx.x * blockDim.x + threadIdx.x;
    float4* __restrict__ y4 = reinterpret_cast<float4*>(g_y32);
    const float4 v = y4[i];
    h4 o;
    o.a = __floats2half2_rn(v.x, v.y);
    o.b = __floats2half2_rn(v.z, v.w);
    reinterpret_cast<h4*>(g_x16)[i] = o;
    y4[i] = make_float4(0.f, 0.f, 0.f, 0.f);
}

// ---------------------------------------------------------------------------
// One hop: y32[obj[t]] += x16[subj[t]] * rt16[rel[t]]  (64-wide batch row)
// 16 threads per group of 4 consecutive triples; 8B fp16 gathers, fp32 math,
// fp32 vector reduction (no rounding inside the segment sum).
// ---------------------------------------------------------------------------
__device__ __forceinline__ void red_v4(float* dst, float4 m) {
    asm volatile("red.global.add.v4.f32 [%0], {%1,%2,%3,%4};"
                 :: "l"(dst), "f"(m.x), "f"(m.y), "f"(m.z), "f"(m.w)
                 : "memory");
}

__device__ __forceinline__ int4 ldcs_int4(const int* p) {
    int4 v;
    asm volatile("ld.global.cs.v4.s32 {%0,%1,%2,%3}, [%4];"
                 : "=r"(v.x), "=r"(v.y), "=r"(v.z), "=r"(v.w) : "l"(p));
    return v;
}

__device__ __forceinline__ float4 hmul4(h4 xv, h4 rv) {
    const float2 xl = __half22float2(xv.a), xh = __half22float2(xv.b);
    const float2 rl = __half22float2(rv.a), rh = __half22float2(rv.b);
    return make_float4(xl.x * rl.x, xl.y * rl.y, xh.x * rh.x, xh.y * rh.y);
}

__global__ void __launch_bounds__(128)
hop_scatter(const int* __restrict__ subj,
            const int* __restrict__ rel,
            const int* __restrict__ obj,
            int hop, const int* __restrict__ n_hop) {
    if (hop >= *n_hop) return;
    const __half* __restrict__ xt = g_x16;
    float*        __restrict__ yt = g_y32;
    const __half* __restrict__ rt = g_rt16[hop];

    const int tid = blockIdx.x * blockDim.x + threadIdx.x;
    const int g   = tid >> 4;                  // triple group of 4
    if (g >= N_T / 4) return;
    const int l16 = tid & 15;
    const int j4  = l16 << 2;                  // float offset within 64-wide row
    const int t0  = g << 2;

    // Streaming index loads (12MB/hop; keep them out of the resident L2 set).
    const int4 s4 = ldcs_int4(subj + t0);
    const int4 r4 = ldcs_int4(rel  + t0);
    const int4 o4 = ldcs_int4(obj  + t0);

    // 4 independent 8B fp16 gathers + 4 rt rows.
    const h4 x0 = reinterpret_cast<const h4*>(xt + (size_t)s4.x * BB)[l16];
    const h4 x1 = reinterpret_cast<const h4*>(xt + (size_t)s4.y * BB)[l16];
    const h4 x2 = reinterpret_cast<const h4*>(xt + (size_t)s4.z * BB)[l16];
    const h4 x3 = reinterpret_cast<const h4*>(xt + (size_t)s4.w * BB)[l16];

    const h4 v0 = reinterpret_cast<const h4*>(rt + r4.x * BB)[l16];
    const h4 v1 = reinterpret_cast<const h4*>(rt + r4.y * BB)[l16];
    const h4 v2 = reinterpret_cast<const h4*>(rt + r4.z * BB)[l16];
    const h4 v3 = reinterpret_cast<const h4*>(rt + r4.w * BB)[l16];

    red_v4(yt + (size_t)o4.x * BB + j4, hmul4(x0, v0));
    red_v4(yt + (size_t)o4.y * BB + j4, hmul4(x1, v1));
    red_v4(yt + (size_t)o4.z * BB + j4, hmul4(x2, v2));
    red_v4(yt + (size_t)o4.w * BB + j4, hmul4(x3, v3));
}

// ---------------------------------------------------------------------------
// Launch
// ---------------------------------------------------------------------------
extern "C" void kernel_launch(void* const* d_in, const int* in_sizes, int n_in,
                              void* d_out, int out_size) {
    const float* x    = (const float*)d_in[0];
    const float* q    = (const float*)d_in[1];
    const float* W1   = (const float*)d_in[2];
    const float* b1   = (const float*)d_in[3];
    const float* W2   = (const float*)d_in[4];
    const float* b2   = (const float*)d_in[5];
    const float* W3   = (const float*)d_in[6];
    const float* b3   = (const float*)d_in[7];
    const int*   subj = (const int*)d_in[8];
    const int*   rel  = (const int*)d_in[9];
    const int*   obj  = (const int*)d_in[10];
    const int*   nhop = (const int*)d_in[11];
    float*       out  = (float*)d_out;

    const int tb = (N_E + 31) / 32;           // 6250 tile blocks

    transpose_in<<<tb, 256>>>(x);             // also zeroes g_y32
    compute_r<<<3 * N_R, 64>>>(q, W1, b1, W2, b2, W3, b3);

    const int scatter_blocks = (N_T / 4 * 16 + 127) / 128;   // 31250
    const int cz_blocks      = (N_E * BB / 4 + 255) / 256;   // 12500

    for (int h = 0; h < 3; ++h) {
        hop_scatter<<<scatter_blocks, 128>>>(subj, rel, obj, h, nhop);
        convert_zero<<<cz_blocks, 256>>>(h, nhop);           // no-op for last hop
    }

    transpose_out<<<tb, 256>>>(out);
}